// round 2
// baseline (speedup 1.0000x reference)
#include <cuda_runtime.h>
#include <cuda_fp16.h>
#include <cstdint>

// ============================================================
// Problem constants
// ============================================================
#define NB 4096   // batch
#define NI 1024   // input dim
#define NO 1024   // output dim
#define K5 5      // control points per edge
#define KP (NI*K5)  // 5120 = GEMM reduction dim

// GEMM tiling (Ampere-style mma.sync pipeline: sm_100 plain target,
// tcgen05 is unavailable because the harness compiles compute_100)
#define BM 128
#define BN 256
#define BK 64
#define NSTAGE 3
#define NCHUNK (KP/BK)          // 80

#define AS_BYTES (BM*BK*2)      // 16384
#define BS_BYTES (BN*BK*2)      // 32768
#define STAGE_BYTES (AS_BYTES + BS_BYTES)   // 49152
#define SMEM_DYN (NSTAGE*STAGE_BYTES)       // 147456

// ============================================================
// Device scratch (allocation-free rule: __device__ globals)
// ============================================================
__device__ __align__(16) __half g_A[(size_t)NB * KP];   // [b][i*5+k] basis fp16
__device__ __align__(16) __half g_B[(size_t)NO * KP];   // [o][i*5+k] importance*coeffs fp16

// ============================================================
// PTX helpers
// ============================================================
__device__ __forceinline__ uint32_t smem_u32(const void* p) {
    uint32_t a;
    asm("{ .reg .u64 t; cvta.to.shared.u64 t, %1; cvt.u32.u64 %0, t; }" : "=r"(a) : "l"(p));
    return a;
}
__device__ __forceinline__ void cp16(uint32_t dst, const void* src) {
    asm volatile("cp.async.cg.shared.global [%0], [%1], 16;" :: "r"(dst), "l"(src));
}
__device__ __forceinline__ void cp_commit() { asm volatile("cp.async.commit_group;"); }
template <int N> __device__ __forceinline__ void cp_wait() {
    asm volatile("cp.async.wait_group %0;" :: "n"(N));
}
__device__ __forceinline__ void ldmx4(uint32_t& r0, uint32_t& r1, uint32_t& r2, uint32_t& r3,
                                      uint32_t addr) {
    asm volatile("ldmatrix.sync.aligned.m8n8.x4.shared.b16 {%0,%1,%2,%3}, [%4];"
                 : "=r"(r0), "=r"(r1), "=r"(r2), "=r"(r3) : "r"(addr));
}
__device__ __forceinline__ void mma16816(float* c,
                                         uint32_t a0, uint32_t a1, uint32_t a2, uint32_t a3,
                                         uint32_t b0, uint32_t b1) {
    asm volatile(
        "mma.sync.aligned.m16n8k16.row.col.f32.f16.f16.f32 "
        "{%0,%1,%2,%3}, {%4,%5,%6,%7}, {%8,%9}, {%0,%1,%2,%3};"
        : "+f"(c[0]), "+f"(c[1]), "+f"(c[2]), "+f"(c[3])
        : "r"(a0), "r"(a1), "r"(a2), "r"(a3), "r"(b0), "r"(b1));
}

// ============================================================
// Kernel 1: closed-form uniform cubic B-spline basis -> g_A fp16
// Uniform knots linspace(-1,1,9): for x in [0,1): s4=floor(4x), u=frac(4x),
// nonzero basis j = s4+1..s4+4 (dropped at j>4), classic cubic weights /6.
// Output staged in smem for vectorized 16B stores.
// ============================================================
__global__ void __launch_bounds__(256) prep_basis(const float* __restrict__ x) {
    __shared__ __half sbuf[256 * K5];   // 2560B
    int base = blockIdx.x * 256;
    int tid = threadIdx.x;
    int idx = base + tid;

    float xi = x[idx];
    float xx = 4.0f * xi;
    float s4f = floorf(xx);
    s4f = fminf(fmaxf(s4f, 0.0f), 3.0f);
    int s4 = (int)s4f;
    float u = xx - s4f;
    float u2 = u * u, u3 = u2 * u;
    float omu = 1.0f - u;
    const float c6 = 1.0f / 6.0f;
    float v[4];
    v[0] = omu * omu * omu * c6;
    v[1] = (3.0f * u3 - 6.0f * u2 + 4.0f) * c6;
    v[2] = (-3.0f * u3 + 3.0f * u2 + 3.0f * u + 1.0f) * c6;
    v[3] = u3 * c6;

    __half h[5];
#pragma unroll
    for (int j = 0; j < 5; j++) h[j] = __float2half(0.0f);
#pragma unroll
    for (int t = 0; t < 4; t++) {
        int j = s4 + 1 + t;
        if (j < 5) h[j] = __float2half(v[t]);
    }
#pragma unroll
    for (int t = 0; t < 5; t++) sbuf[tid * 5 + t] = h[t];
    __syncthreads();

    // 256*5 halves = 2560B = 160 x 16B, contiguous in g_A
    const uint4* s4p = (const uint4*)sbuf;
    uint4* dst = (uint4*)(g_A + (size_t)base * K5);
    if (tid < 160) dst[tid] = s4p[tid];
}

// ============================================================
// Kernel 2: w = importance * coeffs, transposed to [o][i*5+k], fp16
// Coalesced input staging + smem output staging + 16B stores.
// ============================================================
__global__ void __launch_bounds__(256) prep_w(const float* __restrict__ coeffs,
                                              const float* __restrict__ imp) {
    __shared__ float sc[32 * 160];   // [il][ol*5+k]  20KB
    __shared__ float si[32 * 32];    // [il][ol]       4KB
    __shared__ __half sw[32 * 160];  // [ol][il*5+k]  10KB
    int i0 = blockIdx.x * 32;
    int o0 = blockIdx.y * 32;
    int tid = threadIdx.x;

    for (int e = tid; e < 32 * 160; e += 256) {
        int il = e / 160, r = e - il * 160;
        sc[e] = coeffs[((size_t)(i0 + il) * NO + o0) * K5 + r];
    }
    for (int e = tid; e < 1024; e += 256) {
        int il = e >> 5, ol = e & 31;
        si[e] = imp[(size_t)(i0 + il) * NO + o0 + ol];
    }
    __syncthreads();

    for (int f = tid; f < 32 * 160; f += 256) {
        int ol = f / 160, r = f - ol * 160;
        int il = r / 5, k = r - il * 5;
        float w = sc[il * 160 + ol * 5 + k] * si[il * 32 + ol];
        sw[f] = __float2half(w);
    }
    __syncthreads();

    // each ol row: 160 halves = 320B contiguous at g_B[(o0+ol)*KP + i0*5]
    const uint4* swv = (const uint4*)sw;
    for (int v = tid; v < 32 * 20; v += 256) {
        int ol = v / 20, q = v - ol * 20;
        *(uint4*)(g_B + (size_t)(o0 + ol) * KP + (size_t)i0 * 5 + q * 8) = swv[ol * 20 + q];
    }
}

// ============================================================
// Kernel 3: HMMA GEMM  out[4096,1024] = A[4096,5120] * B[1024,5120]^T
// BM=128 BN=256 BK=64, 512 threads (4x4 warps, 32x64 C per warp),
// 3-stage cp.async, xor-swizzled smem, ldmatrix.x4 (TN layout, no trans).
// ============================================================
__global__ void __launch_bounds__(512, 1) kan_gemm(float* __restrict__ out) {
    extern __shared__ char smem[];
    const int tid = threadIdx.x;
    const int wid = tid >> 5, lane = tid & 31;
    const int wr = wid >> 2, wc = wid & 3;   // warp grid 4 (M) x 4 (N)
    const int m0 = blockIdx.x * BM, n0 = blockIdx.y * BN;

    float acc[2][8][4];
#pragma unroll
    for (int i = 0; i < 2; i++)
#pragma unroll
        for (int j = 0; j < 8; j++)
#pragma unroll
            for (int q = 0; q < 4; q++) acc[i][j][q] = 0.f;

    const uint32_t sbase = smem_u32(smem);

    auto issue = [&](int kt) {
        int s = kt % NSTAGE;
        uint32_t as = sbase + s * STAGE_BYTES;
        uint32_t bs = as + AS_BYTES;
        int koff = kt * BK;
        // A tile: 128 rows x 128B (64 halfs), 1024 16B chunks, 2 per thread
#pragma unroll
        for (int i = 0; i < 2; i++) {
            int ca = tid + i * 512;
            int r = ca >> 3, cc = ca & 7;
            cp16(as + r * 128 + (((cc ^ (r & 7)) << 4)),
                 g_A + (size_t)(m0 + r) * KP + koff + cc * 8);
        }
        // B tile: 256 rows x 128B, 2048 chunks, 4 per thread
#pragma unroll
        for (int i = 0; i < 4; i++) {
            int cb = tid + i * 512;
            int r = cb >> 3, cc = cb & 7;
            cp16(bs + r * 128 + (((cc ^ (r & 7)) << 4)),
                 g_B + (size_t)(n0 + r) * KP + koff + cc * 8);
        }
        cp_commit();
    };

    issue(0);
    issue(1);

    const int lrow = lane & 15;       // ldmatrix row within 16
    const int lhalf = lane >> 4;      // 16B half select
    const int lxor = lrow & 7;

    for (int kt = 0; kt < NCHUNK; kt++) {
        if (kt < NCHUNK - 1) cp_wait<1>(); else cp_wait<0>();
        __syncthreads();
        if (kt + 2 < NCHUNK) issue(kt + 2);

        int s = kt % NSTAGE;
        uint32_t as = sbase + s * STAGE_BYTES;
        uint32_t bs = as + AS_BYTES;

#pragma unroll
        for (int ks = 0; ks < 4; ks++) {
            int cc = (ks * 2 + lhalf) ^ lxor;
            uint32_t a[2][4];
#pragma unroll
            for (int mi = 0; mi < 2; mi++) {
                int r = wr * 32 + mi * 16 + lrow;
                ldmx4(a[mi][0], a[mi][1], a[mi][2], a[mi][3], as + r * 128 + cc * 16);
            }
#pragma unroll
            for (int g = 0; g < 4; g++) {
                uint32_t b0, b1, b2, b3;
                int r = wc * 64 + g * 16 + lrow;
                ldmx4(b0, b1, b2, b3, bs + r * 128 + cc * 16);
#pragma unroll
                for (int mi = 0; mi < 2; mi++) {
                    mma16816(acc[mi][g * 2 + 0], a[mi][0], a[mi][1], a[mi][2], a[mi][3], b0, b2);
                    mma16816(acc[mi][g * 2 + 1], a[mi][0], a[mi][1], a[mi][2], a[mi][3], b1, b3);
                }
            }
        }
    }

    // Epilogue: c frag lanes: rows lane/4 (+8), cols 2*(lane%4)+{0,1}
    const int lr = lane >> 2;
    const int lc = (lane & 3) * 2;
#pragma unroll
    for (int mi = 0; mi < 2; mi++) {
#pragma unroll
        for (int nf = 0; nf < 8; nf++) {
            int row = m0 + wr * 32 + mi * 16 + lr;
            int col = n0 + wc * 64 + nf * 8 + lc;
            float* p = out + (size_t)row * NO + col;
            *(float2*)p = make_float2(acc[mi][nf][0], acc[mi][nf][1]);
            *(float2*)(p + 8 * NO) = make_float2(acc[mi][nf][2], acc[mi][nf][3]);
        }
    }
}

// ============================================================
// Launch
// ============================================================
extern "C" void kernel_launch(void* const* d_in, const int* in_sizes, int n_in,
                              void* d_out, int out_size) {
    const float* x = nullptr;
    const float* coeffs = nullptr;
    const float* imp = nullptr;
    for (int i = 0; i < n_in; i++) {
        if (in_sizes[i] == NB * NI) x = (const float*)d_in[i];
        else if (in_sizes[i] == NI * NO * K5) coeffs = (const float*)d_in[i];
        else if (in_sizes[i] == NI * NO) imp = (const float*)d_in[i];
    }

    prep_basis<<<(NB * NI) / 256, 256>>>(x);
    prep_w<<<dim3(NI / 32, NO / 32), 256>>>(coeffs, imp);

    static int smem_set = 0;
    if (!smem_set) {
        cudaFuncSetAttribute(kan_gemm, cudaFuncAttributeMaxDynamicSharedMemorySize, SMEM_DYN);
        smem_set = 1;
    }
    kan_gemm<<<dim3(NB / BM, NO / BN), 512, SMEM_DYN>>>((float*)d_out);
}